// round 6
// baseline (speedup 1.0000x reference)
#include <cuda_runtime.h>

// GroupAvgPool1d: feature[b,g,c] = sum_{n: y[b,n]==g} x[b,n,c] / N ; mask[b,g] = count>0
// Shapes: B=16, N=8192, C=64, G=512. y is int32 on device.
#define BB 16
#define NN 8192
#define CC 64
#define GG 512

#define THREADS 256            // 8 warps per CTA
#define GROUPS_PER_WARP 8      // two sets of 4
#define GROUPS_PER_CTA 64      // 8 warps * 8 groups
#define CTAS_PER_BATCH 8       // 512 / 64
#define NSPLIT 8
#define SLICE (NN / NSPLIT)    // 1024 rows per CTA

#define FEAT_ELEMS (BB * GG * CC)   // 524288 floats

// ---------------------------------------------------------------------------
// Init kernel: zero the feature region; CTAs 0..15 also compute mask[b,:].
// ---------------------------------------------------------------------------
__global__ __launch_bounds__(256)
void init_kernel(const int* __restrict__ y, float* __restrict__ out)
{
    float4* f4 = (float4*)out;
    const int n4 = FEAT_ELEMS / 4;
    for (int i = blockIdx.x * 256 + threadIdx.x; i < n4; i += gridDim.x * 256)
        f4[i] = make_float4(0.f, 0.f, 0.f, 0.f);

    if (blockIdx.x < BB) {
        const int b = blockIdx.x;
        __shared__ int flag[GG];
        for (int g = threadIdx.x; g < GG; g += 256) flag[g] = 0;
        __syncthreads();
        const int* yb = y + b * NN;
        for (int i = threadIdx.x; i < NN; i += 256) {
            unsigned g = (unsigned)yb[i];
            if (g < GG) flag[g] = 1;
        }
        __syncthreads();
        float* mout = out + FEAT_ELEMS + b * GG;
        for (int g = threadIdx.x; g < GG; g += 256)
            mout[g] = flag[g] ? 1.0f : 0.0f;
    }
}

// ---------------------------------------------------------------------------
// Accumulation kernel: each warp owns TWO 4-group sets; one y-window read
// feeds two ballots, halving scan work per owned group.
// ---------------------------------------------------------------------------
__device__ __forceinline__ void red_add2(float2* p, float x, float yv)
{
    asm volatile("red.global.add.v2.f32 [%0], {%1, %2};"
                 :: "l"(p), "f"(x), "f"(yv) : "memory");
}

#define PROCESS_WINDOW(bal, yv, base, A0, A1, A2, A3)                      \
    while (bal) {                                                          \
        int src = __ffs(bal) - 1;                                          \
        bal &= bal - 1;                                                    \
        int info = __shfl_sync(0xffffffffu, (yv), src);                    \
        int row  = (base) + src;                                           \
        float2 v = xb[row * 32 + lane];                                    \
        int which = info & 3;                                              \
        if (which == 0)      { A0.x += v.x; A0.y += v.y; }                 \
        else if (which == 1) { A1.x += v.x; A1.y += v.y; }                 \
        else if (which == 2) { A2.x += v.x; A2.y += v.y; }                 \
        else                 { A3.x += v.x; A3.y += v.y; }                 \
    }

__global__ __launch_bounds__(THREADS)
void accum_kernel(const float* __restrict__ x,
                  const int* __restrict__ y,
                  float* __restrict__ out)
{
    __shared__ int sy[SLICE];   // 4 KB: this CTA's y slice

    const int b    = blockIdx.y;
    const int gblk = blockIdx.x;
    const int ns   = blockIdx.z;
    const int tid  = threadIdx.x;
    const int rbase = ns * SLICE;

    // Stage y slice with int4 loads (1 per thread).
    {
        const int4* y4 = (const int4*)(y + b * NN + rbase);
        int4* sy4 = (int4*)sy;
        #pragma unroll
        for (int i = tid; i < SLICE / 4; i += THREADS)
            sy4[i] = y4[i];
    }
    __syncthreads();

    const int warp = tid >> 5;
    const int lane = tid & 31;

    // Set A: groups [gbaseA, gbaseA+4); Set B: groups [gbaseA+32, gbaseA+36).
    const int gbaseA = gblk * GROUPS_PER_CTA + warp * 4;
    const int gbaseB = gbaseA + 32;
    const unsigned kqA = (unsigned)(gbaseA >> 2);
    const unsigned kqB = kqA + 8;

    const float2* xb = (const float2*)(x + ((long long)b * NN + rbase) * CC);

    float2 a0 = {0.f,0.f}, a1 = {0.f,0.f}, a2 = {0.f,0.f}, a3 = {0.f,0.f};
    float2 e0 = {0.f,0.f}, e1 = {0.f,0.f}, e2 = {0.f,0.f}, e3 = {0.f,0.f};

    #pragma unroll
    for (int base = 0; base < SLICE; base += 128) {
        int yv0 = sy[base + lane];
        int yv1 = sy[base + 32 + lane];
        int yv2 = sy[base + 64 + lane];
        int yv3 = sy[base + 96 + lane];
        unsigned q0 = (unsigned)yv0 >> 2;
        unsigned q1 = (unsigned)yv1 >> 2;
        unsigned q2 = (unsigned)yv2 >> 2;
        unsigned q3 = (unsigned)yv3 >> 2;
        unsigned bA0 = __ballot_sync(0xffffffffu, q0 == kqA);
        unsigned bA1 = __ballot_sync(0xffffffffu, q1 == kqA);
        unsigned bA2 = __ballot_sync(0xffffffffu, q2 == kqA);
        unsigned bA3 = __ballot_sync(0xffffffffu, q3 == kqA);
        unsigned bB0 = __ballot_sync(0xffffffffu, q0 == kqB);
        unsigned bB1 = __ballot_sync(0xffffffffu, q1 == kqB);
        unsigned bB2 = __ballot_sync(0xffffffffu, q2 == kqB);
        unsigned bB3 = __ballot_sync(0xffffffffu, q3 == kqB);
        PROCESS_WINDOW(bA0, yv0, base,      a0, a1, a2, a3)
        PROCESS_WINDOW(bA1, yv1, base + 32, a0, a1, a2, a3)
        PROCESS_WINDOW(bA2, yv2, base + 64, a0, a1, a2, a3)
        PROCESS_WINDOW(bA3, yv3, base + 96, a0, a1, a2, a3)
        PROCESS_WINDOW(bB0, yv0, base,      e0, e1, e2, e3)
        PROCESS_WINDOW(bB1, yv1, base + 32, e0, e1, e2, e3)
        PROCESS_WINDOW(bB2, yv2, base + 64, e0, e1, e2, e3)
        PROCESS_WINDOW(bB3, yv3, base + 96, e0, e1, e2, e3)
    }

    // Reduce partials into the output (feature region pre-zeroed by init_kernel).
    const float scale = 1.0f / (float)NN;
    float2* fout = (float2*)out;
    const int fbA = (b * GG + gbaseA) * 32 + lane;
    const int fbB = (b * GG + gbaseB) * 32 + lane;
    red_add2(fout + fbA + 0 * 32, a0.x * scale, a0.y * scale);
    red_add2(fout + fbA + 1 * 32, a1.x * scale, a1.y * scale);
    red_add2(fout + fbA + 2 * 32, a2.x * scale, a2.y * scale);
    red_add2(fout + fbA + 3 * 32, a3.x * scale, a3.y * scale);
    red_add2(fout + fbB + 0 * 32, e0.x * scale, e0.y * scale);
    red_add2(fout + fbB + 1 * 32, e1.x * scale, e1.y * scale);
    red_add2(fout + fbB + 2 * 32, e2.x * scale, e2.y * scale);
    red_add2(fout + fbB + 3 * 32, e3.x * scale, e3.y * scale);
}

extern "C" void kernel_launch(void* const* d_in, const int* in_sizes, int n_in,
                              void* d_out, int out_size)
{
    const float* x = (const float*)d_in[0];
    const int*   y = (const int*)d_in[1];
    float*     out = (float*)d_out;

    init_kernel<<<148, 256>>>(y, out);

    dim3 grid(CTAS_PER_BATCH, BB, NSPLIT);   // 8 x 16 x 8 = 1024 CTAs
    accum_kernel<<<grid, THREADS>>>(x, y, out);
}

// round 7
// speedup vs baseline: 1.0598x; 1.0598x over previous
#include <cuda_runtime.h>

// GroupAvgPool1d: feature[b,g,c] = sum_{n: y[b,n]==g} x[b,n,c] / N ; mask[b,g] = count>0
// Shapes: B=16, N=8192, C=64, G=512. y is int32 on device.
#define BB 16
#define NN 8192
#define CC 64
#define GG 512

#define THREADS 256            // 8 warps per CTA
#define GROUPS_PER_WARP 4
#define GROUPS_PER_CTA 32      // 8 warps * 4 groups
#define CTAS_PER_BATCH 16      // 512 / 32
#define NSPLIT 16
#define SLICE (NN / NSPLIT)    // 512 rows per CTA

#define FEAT_ELEMS (BB * GG * CC)   // 524288 floats

// ---------------------------------------------------------------------------
// Init kernel: zero the feature region; CTAs 0..15 also compute mask[b,:].
// ---------------------------------------------------------------------------
__global__ __launch_bounds__(256)
void init_kernel(const int* __restrict__ y, float* __restrict__ out)
{
    float4* f4 = (float4*)out;
    const int n4 = FEAT_ELEMS / 4;
    for (int i = blockIdx.x * 256 + threadIdx.x; i < n4; i += gridDim.x * 256)
        f4[i] = make_float4(0.f, 0.f, 0.f, 0.f);

    if (blockIdx.x < BB) {
        const int b = blockIdx.x;
        __shared__ int flag[GG];
        for (int g = threadIdx.x; g < GG; g += 256) flag[g] = 0;
        __syncthreads();
        const int* yb = y + b * NN;
        for (int i = threadIdx.x; i < NN; i += 256) {
            unsigned g = (unsigned)yb[i];
            if (g < GG) flag[g] = 1;
        }
        __syncthreads();
        float* mout = out + FEAT_ELEMS + b * GG;
        for (int g = threadIdx.x; g < GG; g += 256)
            mout[g] = flag[g] ? 1.0f : 0.0f;
    }
}

// ---------------------------------------------------------------------------
// Accumulation kernel: ownership-partitioned gather over an N-slice, then
// global float reductions into the feature output.
// ---------------------------------------------------------------------------
__device__ __forceinline__ void red_add2(float2* p, float x, float yv)
{
    asm volatile("red.global.add.v2.f32 [%0], {%1, %2};"
                 :: "l"(p), "f"(x), "f"(yv) : "memory");
}

#define PROCESS_WINDOW(bal, yv, base)                                      \
    while (bal) {                                                          \
        int src = __ffs(bal) - 1;                                          \
        bal &= bal - 1;                                                    \
        int info = __shfl_sync(0xffffffffu, (yv), src);                    \
        int row  = (base) + src;                                           \
        float2 v = xb[row * 32 + lane];                                    \
        int which = info & 3;                                              \
        if (which == 0)      { a0.x += v.x; a0.y += v.y; }                 \
        else if (which == 1) { a1.x += v.x; a1.y += v.y; }                 \
        else if (which == 2) { a2.x += v.x; a2.y += v.y; }                 \
        else                 { a3.x += v.x; a3.y += v.y; }                 \
    }

__global__ __launch_bounds__(THREADS)
void accum_kernel(const float* __restrict__ x,
                  const int* __restrict__ y,
                  float* __restrict__ out)
{
    __shared__ int sy[SLICE];   // 2 KB: this CTA's y slice

    const int b    = blockIdx.y;
    const int gblk = blockIdx.x;
    const int ns   = blockIdx.z;
    const int tid  = threadIdx.x;
    const int rbase = ns * SLICE;

    // Stage y slice with int4 loads (first 128 threads, 1 each).
    {
        const int4* y4 = (const int4*)(y + b * NN + rbase);
        int4* sy4 = (int4*)sy;
        if (tid < SLICE / 4)
            sy4[tid] = y4[tid];
    }
    __syncthreads();

    const int warp = tid >> 5;
    const int lane = tid & 31;

    const int gbase = gblk * GROUPS_PER_CTA + warp * GROUPS_PER_WARP;
    const unsigned kq = (unsigned)(gbase >> 2);

    const float2* xb = (const float2*)(x + ((long long)b * NN + rbase) * CC);

    float2 a0 = {0.f, 0.f}, a1 = {0.f, 0.f}, a2 = {0.f, 0.f}, a3 = {0.f, 0.f};

    #pragma unroll
    for (int base = 0; base < SLICE; base += 128) {
        int yv0 = sy[base + lane];
        int yv1 = sy[base + 32 + lane];
        int yv2 = sy[base + 64 + lane];
        int yv3 = sy[base + 96 + lane];
        unsigned b0 = __ballot_sync(0xffffffffu, ((unsigned)yv0 >> 2) == kq);
        unsigned b1 = __ballot_sync(0xffffffffu, ((unsigned)yv1 >> 2) == kq);
        unsigned b2 = __ballot_sync(0xffffffffu, ((unsigned)yv2 >> 2) == kq);
        unsigned b3 = __ballot_sync(0xffffffffu, ((unsigned)yv3 >> 2) == kq);
        PROCESS_WINDOW(b0, yv0, base)
        PROCESS_WINDOW(b1, yv1, base + 32)
        PROCESS_WINDOW(b2, yv2, base + 64)
        PROCESS_WINDOW(b3, yv3, base + 96)
    }

    // Reduce partials into the output (feature region pre-zeroed by init_kernel).
    const float scale = 1.0f / (float)NN;
    float2* fout = (float2*)out;
    const int fb = (b * GG + gbase) * 32 + lane;
    red_add2(fout + fb + 0 * 32, a0.x * scale, a0.y * scale);
    red_add2(fout + fb + 1 * 32, a1.x * scale, a1.y * scale);
    red_add2(fout + fb + 2 * 32, a2.x * scale, a2.y * scale);
    red_add2(fout + fb + 3 * 32, a3.x * scale, a3.y * scale);
}

extern "C" void kernel_launch(void* const* d_in, const int* in_sizes, int n_in,
                              void* d_out, int out_size)
{
    const float* x = (const float*)d_in[0];
    const int*   y = (const int*)d_in[1];
    float*     out = (float*)d_out;

    init_kernel<<<148, 256>>>(y, out);

    dim3 grid(CTAS_PER_BATCH, BB, NSPLIT);   // 16 x 16 x 16 = 4096 CTAs
    accum_kernel<<<grid, THREADS>>>(x, y, out);
}